// round 1
// baseline (speedup 1.0000x reference)
#include <cuda_runtime.h>
#include <math.h>

// Problem constants
#define BATCH 2
#define SEQ   2048
#define HID   1024
#define NHEAD 16
#define DHEAD 64
#define MTOT  (BATCH * SEQ)        // 4096 rows

// Scratch (device globals: allocation-free per harness rules)
__device__ float g_qkv[(size_t)MTOT * 3 * HID];   // [4096, 3072]
__device__ float g_attn[(size_t)MTOT * HID];      // [4096, 1024]

// ---------------------------------------------------------------------------
// SGEMM: C[M,N] = A[M,K] @ B[K,N] + bias[N]
// 128x128 block tile, BK=8, 256 threads, 8x8 per-thread microtile.
// ---------------------------------------------------------------------------
#define GBM 128
#define GBN 128
#define GBK 8

__global__ __launch_bounds__(256) void sgemm_bias_kernel(
    const float* __restrict__ A, const float* __restrict__ B,
    const float* __restrict__ bias, float* __restrict__ C,
    int M, int N, int K)
{
    __shared__ float As[GBK][GBM];
    __shared__ float Bs[GBK][GBN];

    const int tid = threadIdx.x;
    const int tx  = tid & 15;      // 0..15 -> 8 cols each
    const int ty  = tid >> 4;      // 0..15 -> 8 rows each

    const int row0 = blockIdx.y * GBM;
    const int col0 = blockIdx.x * GBN;

    // A tile loader: 128 rows x 8 cols, one float4 per thread
    const int aRow = tid >> 1;           // 0..127
    const int aCol = (tid & 1) * 4;      // 0 or 4
    // B tile loader: 8 rows x 128 cols, one float4 per thread
    const int bRow = tid >> 5;           // 0..7
    const int bCol = (tid & 31) * 4;     // 0..124

    const float* Ap = A + (size_t)(row0 + aRow) * K + aCol;
    const float* Bp = B + (size_t)bRow * N + col0 + bCol;

    float acc[8][8];
    #pragma unroll
    for (int i = 0; i < 8; i++)
        #pragma unroll
        for (int j = 0; j < 8; j++) acc[i][j] = 0.0f;

    for (int k0 = 0; k0 < K; k0 += GBK) {
        float4 a4 = *(const float4*)Ap;
        float4 b4 = *(const float4*)Bp;
        As[aCol + 0][aRow] = a4.x;
        As[aCol + 1][aRow] = a4.y;
        As[aCol + 2][aRow] = a4.z;
        As[aCol + 3][aRow] = a4.w;
        *(float4*)&Bs[bRow][bCol] = b4;
        __syncthreads();

        #pragma unroll
        for (int k = 0; k < GBK; k++) {
            float a[8], b[8];
            *(float4*)&a[0] = *(const float4*)&As[k][ty * 8];
            *(float4*)&a[4] = *(const float4*)&As[k][ty * 8 + 4];
            *(float4*)&b[0] = *(const float4*)&Bs[k][tx * 8];
            *(float4*)&b[4] = *(const float4*)&Bs[k][tx * 8 + 4];
            #pragma unroll
            for (int i = 0; i < 8; i++)
                #pragma unroll
                for (int j = 0; j < 8; j++)
                    acc[i][j] = fmaf(a[i], b[j], acc[i][j]);
        }
        __syncthreads();

        Ap += GBK;
        Bp += (size_t)GBK * N;
    }

    #pragma unroll
    for (int i = 0; i < 8; i++) {
        const int r = row0 + ty * 8 + i;
        #pragma unroll
        for (int j = 0; j < 8; j += 4) {
            const int c = col0 + tx * 8 + j;
            float4 o;
            o.x = acc[i][j + 0] + bias[c + 0];
            o.y = acc[i][j + 1] + bias[c + 1];
            o.z = acc[i][j + 2] + bias[c + 2];
            o.w = acc[i][j + 3] + bias[c + 3];
            *(float4*)&C[(size_t)r * N + c] = o;
        }
    }
}

// ---------------------------------------------------------------------------
// Flash attention (causal), fp32.
// Grid: (SEQ/64, BATCH*NHEAD). 256 threads. 64x64 Q/K tiles, DK=64.
// Thread (ty,tx) in 16x16 grid owns a 4x4 microtile of S and O.
// P is staged through the K smem buffer (after a barrier) to save smem.
// qkv layout: [4096, 3072]; q at col h*64, k at 1024+h*64, v at 2048+h*64.
// ---------------------------------------------------------------------------
#define FBM 64
#define FBN 64
#define FPAD 4
#define FSTR (DHEAD + FPAD)   // 68
#define FSMEM (3 * FBM * FSTR * 4)   // 52224 bytes

__global__ __launch_bounds__(256) void flash_attn_kernel(
    const float* __restrict__ qkv, float* __restrict__ out)
{
    extern __shared__ float sm[];
    float* Qs = sm;                       // FBM * FSTR
    float* Ks = Qs + FBM * FSTR;          // FBN * FSTR (reused for P)
    float* Vs = Ks + FBN * FSTR;          // FBN * FSTR

    const int tid = threadIdx.x;
    const int tx = tid & 15;
    const int ty = tid >> 4;

    const int bh = blockIdx.y;
    const int b  = bh >> 4;               // / NHEAD
    const int h  = bh & 15;               // % NHEAD
    const int q0 = blockIdx.x * FBM;

    const float scale = 0.125f;           // 1/sqrt(64)

    // Load Q tile (scaled)
    for (int i = tid; i < FBM * (DHEAD / 4); i += 256) {
        const int r  = i >> 4;            // /16
        const int d4 = (i & 15) * 4;
        float4 v = *(const float4*)(qkv + (size_t)(b * SEQ + q0 + r) * (3 * HID) + h * DHEAD + d4);
        float4 s4 = make_float4(v.x * scale, v.y * scale, v.z * scale, v.w * scale);
        *(float4*)&Qs[r * FSTR + d4] = s4;
    }

    float m[4], l[4], acc[4][4];
    #pragma unroll
    for (int i = 0; i < 4; i++) {
        m[i] = -INFINITY;
        l[i] = 0.0f;
        #pragma unroll
        for (int j = 0; j < 4; j++) acc[i][j] = 0.0f;
    }

    const int ktiles = (q0 / FBN) + 1;    // causal: only tiles with k0 <= q0

    for (int kt = 0; kt < ktiles; kt++) {
        const int k0 = kt * FBN;
        __syncthreads();  // previous P/V reads done (also covers Q load on iter 0)

        // Load K and V tiles
        for (int i = tid; i < FBN * (DHEAD / 4); i += 256) {
            const int r  = i >> 4;
            const int d4 = (i & 15) * 4;
            const size_t base = (size_t)(b * SEQ + k0 + r) * (3 * HID) + h * DHEAD + d4;
            *(float4*)&Ks[r * FSTR + d4] = *(const float4*)(qkv + base + HID);
            *(float4*)&Vs[r * FSTR + d4] = *(const float4*)(qkv + base + 2 * HID);
        }
        __syncthreads();

        // S = Qs @ Ks^T (4x4 microtile)
        float S[4][4];
        #pragma unroll
        for (int i = 0; i < 4; i++)
            #pragma unroll
            for (int j = 0; j < 4; j++) S[i][j] = 0.0f;

        #pragma unroll 4
        for (int d = 0; d < DHEAD; d += 4) {
            float4 qa[4], kb[4];
            #pragma unroll
            for (int i = 0; i < 4; i++) qa[i] = *(const float4*)&Qs[(ty * 4 + i) * FSTR + d];
            #pragma unroll
            for (int j = 0; j < 4; j++) kb[j] = *(const float4*)&Ks[(tx * 4 + j) * FSTR + d];
            #pragma unroll
            for (int i = 0; i < 4; i++)
                #pragma unroll
                for (int j = 0; j < 4; j++) {
                    S[i][j] = fmaf(qa[i].x, kb[j].x, S[i][j]);
                    S[i][j] = fmaf(qa[i].y, kb[j].y, S[i][j]);
                    S[i][j] = fmaf(qa[i].z, kb[j].z, S[i][j]);
                    S[i][j] = fmaf(qa[i].w, kb[j].w, S[i][j]);
                }
        }

        // Causal mask: only the diagonal tile needs it (k0 == q0)
        if (kt == ktiles - 1) {
            #pragma unroll
            for (int i = 0; i < 4; i++)
                #pragma unroll
                for (int j = 0; j < 4; j++)
                    if (tx * 4 + j > ty * 4 + i) S[i][j] = -INFINITY;
        }

        // Online softmax update per row
        #pragma unroll
        for (int i = 0; i < 4; i++) {
            float rmax = fmaxf(fmaxf(S[i][0], S[i][1]), fmaxf(S[i][2], S[i][3]));
            #pragma unroll
            for (int o = 8; o >= 1; o >>= 1)
                rmax = fmaxf(rmax, __shfl_xor_sync(0xffffffffu, rmax, o));
            const float mnew = fmaxf(m[i], rmax);
            const float alpha = __expf(m[i] - mnew);
            float rsum = 0.0f;
            #pragma unroll
            for (int j = 0; j < 4; j++) {
                const float p = __expf(S[i][j] - mnew);
                S[i][j] = p;
                rsum += p;
            }
            #pragma unroll
            for (int o = 8; o >= 1; o >>= 1)
                rsum += __shfl_xor_sync(0xffffffffu, rsum, o);
            l[i] = l[i] * alpha + rsum;
            m[i] = mnew;
            #pragma unroll
            for (int j = 0; j < 4; j++) acc[i][j] *= alpha;
        }

        __syncthreads();   // everyone done reading Ks
        // Stage P into the K buffer
        #pragma unroll
        for (int i = 0; i < 4; i++)
            #pragma unroll
            for (int j = 0; j < 4; j++)
                Ks[(ty * 4 + i) * FSTR + tx * 4 + j] = S[i][j];
        __syncthreads();

        // O += P @ V
        #pragma unroll 4
        for (int k = 0; k < FBN; k += 4) {
            float4 p4[4];
            float4 v4[4];
            #pragma unroll
            for (int i = 0; i < 4; i++) p4[i] = *(const float4*)&Ks[(ty * 4 + i) * FSTR + k];
            #pragma unroll
            for (int kk = 0; kk < 4; kk++) v4[kk] = *(const float4*)&Vs[(k + kk) * FSTR + tx * 4];
            #pragma unroll
            for (int i = 0; i < 4; i++) {
                acc[i][0] = fmaf(p4[i].x, v4[0].x, acc[i][0]);
                acc[i][1] = fmaf(p4[i].x, v4[0].y, acc[i][1]);
                acc[i][2] = fmaf(p4[i].x, v4[0].z, acc[i][2]);
                acc[i][3] = fmaf(p4[i].x, v4[0].w, acc[i][3]);
                acc[i][0] = fmaf(p4[i].y, v4[1].x, acc[i][0]);
                acc[i][1] = fmaf(p4[i].y, v4[1].y, acc[i][1]);
                acc[i][2] = fmaf(p4[i].y, v4[1].z, acc[i][2]);
                acc[i][3] = fmaf(p4[i].y, v4[1].w, acc[i][3]);
                acc[i][0] = fmaf(p4[i].z, v4[2].x, acc[i][0]);
                acc[i][1] = fmaf(p4[i].z, v4[2].y, acc[i][1]);
                acc[i][2] = fmaf(p4[i].z, v4[2].z, acc[i][2]);
                acc[i][3] = fmaf(p4[i].z, v4[2].w, acc[i][3]);
                acc[i][0] = fmaf(p4[i].w, v4[3].x, acc[i][0]);
                acc[i][1] = fmaf(p4[i].w, v4[3].y, acc[i][1]);
                acc[i][2] = fmaf(p4[i].w, v4[3].z, acc[i][2]);
                acc[i][3] = fmaf(p4[i].w, v4[3].w, acc[i][3]);
            }
        }
    }

    // Normalize and write O: [B,S,H] layout, head h at cols h*64..h*64+63
    #pragma unroll
    for (int i = 0; i < 4; i++) {
        const float inv = 1.0f / l[i];
        const int s = q0 + ty * 4 + i;
        float4 o;
        o.x = acc[i][0] * inv;
        o.y = acc[i][1] * inv;
        o.z = acc[i][2] * inv;
        o.w = acc[i][3] * inv;
        *(float4*)&out[(size_t)(b * SEQ + s) * HID + h * DHEAD + tx * 4] = o;
    }
}

// ---------------------------------------------------------------------------
// Launch
// ---------------------------------------------------------------------------
extern "C" void kernel_launch(void* const* d_in, const int* in_sizes, int n_in,
                              void* d_out, int out_size)
{
    const float* x      = (const float*)d_in[0];   // [B,S,H]
    const float* w_attn = (const float*)d_in[1];   // [H, 3H]
    const float* b_attn = (const float*)d_in[2];   // [3H]
    const float* w_proj = (const float*)d_in[3];   // [H, H]
    const float* b_proj = (const float*)d_in[4];   // [H]
    float* out = (float*)d_out;                    // [B,S,H]

    float *qkv, *attn;
    cudaGetSymbolAddress((void**)&qkv,  g_qkv);
    cudaGetSymbolAddress((void**)&attn, g_attn);

    // 1) QKV projection: [4096,1024] @ [1024,3072] + b_attn
    {
        dim3 grid((3 * HID) / GBN, MTOT / GBM);
        sgemm_bias_kernel<<<grid, 256>>>(x, w_attn, b_attn, qkv, MTOT, 3 * HID, HID);
    }

    // 2) Causal flash attention
    {
        cudaFuncSetAttribute(flash_attn_kernel,
                             cudaFuncAttributeMaxDynamicSharedMemorySize, FSMEM);
        dim3 grid(SEQ / FBM, BATCH * NHEAD);
        flash_attn_kernel<<<grid, 256, FSMEM>>>(qkv, attn);
    }

    // 3) Output projection: [4096,1024] @ [1024,1024] + b_proj
    {
        dim3 grid(HID / GBN, MTOT / GBM);
        sgemm_bias_kernel<<<grid, 256>>>(attn, w_proj, b_proj, out, MTOT, HID, HID);
    }
}

// round 3
// speedup vs baseline: 3.0278x; 3.0278x over previous
#include <cuda_runtime.h>
#include <cuda_bf16.h>
#include <math.h>
#include <stdint.h>
#include <string.h>

// Problem constants
#define BATCH 2
#define SEQ   2048
#define HID   1024
#define NHEAD 16
#define DHEAD 64
#define MTOT  (BATCH * SEQ)        // 4096 rows

// ---------------------------------------------------------------------------
// Scratch (device globals: allocation-free per harness rules)
// ---------------------------------------------------------------------------
__device__ __nv_bfloat16 g_xhi[(size_t)MTOT * HID];
__device__ __nv_bfloat16 g_xlo[(size_t)MTOT * HID];
__device__ __nv_bfloat16 g_qkvh[(size_t)MTOT * 3 * HID];
__device__ __nv_bfloat16 g_qkvl[(size_t)MTOT * 3 * HID];
__device__ __nv_bfloat16 g_ahi[(size_t)MTOT * HID];
__device__ __nv_bfloat16 g_alo[(size_t)MTOT * HID];
__device__ __nv_bfloat16 g_wahi[(size_t)3 * HID * HID];   // [3H, H] transposed
__device__ __nv_bfloat16 g_walo[(size_t)3 * HID * HID];
__device__ __nv_bfloat16 g_wphi[(size_t)HID * HID];       // [H, H] transposed
__device__ __nv_bfloat16 g_wplo[(size_t)HID * HID];

// ---------------------------------------------------------------------------
// Helpers
// ---------------------------------------------------------------------------
__device__ __forceinline__ uint32_t smem_u32(const void* p) {
    uint32_t a;
    asm("{ .reg .u64 t; cvta.to.shared.u64 t, %1; cvt.u32.u64 %0, t; }" : "=r"(a) : "l"(p));
    return a;
}

__device__ __forceinline__ void cpa16(uint32_t dst, const void* src) {
    asm volatile("cp.async.cg.shared.global [%0], [%1], 16;" :: "r"(dst), "l"(src));
}
#define CP_COMMIT() asm volatile("cp.async.commit_group;" ::: "memory")
#define CP_WAIT0()  asm volatile("cp.async.wait_group 0;" ::: "memory")
#define CP_WAIT1()  asm volatile("cp.async.wait_group 1;" ::: "memory")

__device__ __forceinline__ void ldm4(uint32_t* r, uint32_t a) {
    asm volatile("ldmatrix.sync.aligned.m8n8.x4.shared.b16 {%0,%1,%2,%3}, [%4];"
                 : "=r"(r[0]), "=r"(r[1]), "=r"(r[2]), "=r"(r[3]) : "r"(a));
}
__device__ __forceinline__ void ldm4t(uint32_t* r, uint32_t a) {
    asm volatile("ldmatrix.sync.aligned.m8n8.x4.trans.shared.b16 {%0,%1,%2,%3}, [%4];"
                 : "=r"(r[0]), "=r"(r[1]), "=r"(r[2]), "=r"(r[3]) : "r"(a));
}

// D(+=): m16n8k16 row.col bf16 -> f32
__device__ __forceinline__ void mma16816(float* d, const uint32_t* a, uint32_t b0, uint32_t b1) {
    asm volatile(
        "mma.sync.aligned.m16n8k16.row.col.f32.bf16.bf16.f32 "
        "{%0,%1,%2,%3}, {%4,%5,%6,%7}, {%8,%9}, {%0,%1,%2,%3};"
        : "+f"(d[0]), "+f"(d[1]), "+f"(d[2]), "+f"(d[3])
        : "r"(a[0]), "r"(a[1]), "r"(a[2]), "r"(a[3]), "r"(b0), "r"(b1));
}

__device__ __forceinline__ uint32_t pack2(__nv_bfloat16 lo, __nv_bfloat16 hi) {
    union { __nv_bfloat162 v; uint32_t u; } c;
    c.v.x = lo; c.v.y = hi;
    return c.u;
}

__device__ __forceinline__ void split1(float v, __nv_bfloat16& h, __nv_bfloat16& l) {
    h = __float2bfloat16(v);
    l = __float2bfloat16(v - __bfloat162float(h));
}

// ---------------------------------------------------------------------------
// Conversion kernels
// ---------------------------------------------------------------------------
__global__ __launch_bounds__(256) void split_kernel(
    const float* __restrict__ in, __nv_bfloat16* __restrict__ hi,
    __nv_bfloat16* __restrict__ lo, int n4)
{
    int i = blockIdx.x * blockDim.x + threadIdx.x;
    if (i >= n4) return;
    float4 v = ((const float4*)in)[i];
    __nv_bfloat16 h0, h1, h2, h3, l0, l1, l2, l3;
    split1(v.x, h0, l0); split1(v.y, h1, l1); split1(v.z, h2, l2); split1(v.w, h3, l3);
    ((uint32_t*)hi)[i * 2]     = pack2(h0, h1);
    ((uint32_t*)hi)[i * 2 + 1] = pack2(h2, h3);
    ((uint32_t*)lo)[i * 2]     = pack2(l0, l1);
    ((uint32_t*)lo)[i * 2 + 1] = pack2(l2, l3);
}

// in: [K_, N_] fp32 row-major -> out hi/lo: [N_, K_] bf16 row-major
__global__ __launch_bounds__(256) void tsplit_kernel(
    const float* __restrict__ in, __nv_bfloat16* __restrict__ hi,
    __nv_bfloat16* __restrict__ lo, int K_, int N_)
{
    __shared__ float t[32][33];
    const int n0 = blockIdx.x * 32;
    const int k0 = blockIdx.y * 32;
    const int tx = threadIdx.x & 31;
    const int ty = threadIdx.x >> 5;
    #pragma unroll
    for (int i = 0; i < 32; i += 8)
        t[ty + i][tx] = in[(size_t)(k0 + ty + i) * N_ + n0 + tx];
    __syncthreads();
    #pragma unroll
    for (int i = 0; i < 32; i += 8) {
        float v = t[tx][ty + i];
        __nv_bfloat16 h, l;
        split1(v, h, l);
        const size_t o = (size_t)(n0 + ty + i) * K_ + k0 + tx;
        hi[o] = h;
        lo[o] = l;
    }
}

// ---------------------------------------------------------------------------
// mma.sync split-bf16 GEMM: C[M,N] = A[M,K]@B[K,N] + bias
// A hi/lo [M,K]; B hi/lo transposed [N,K]. M=4096, K=1024.
// 128x128 CTA tile, BK=32, 8 warps (4x2), warp tile 32x64.
// Smem rows: 80B stride (conflict-free ldmatrix without swizzle).
// mode 0: C fp32.  mode 1: C split to Chi/Clo bf16.
// ---------------------------------------------------------------------------
#define GMAT 10240                 // 128 rows * 80B
#define GSTAGE (4 * GMAT)          // Ah|Al|Bh|Bl = 40960
#define GSMEM (2 * GSTAGE)         // 81920
#define GNCH (HID / 32)            // 32 k-chunks

__device__ __forceinline__ void g_load_stage(
    uint32_t sb, int tid,
    const __nv_bfloat16* __restrict__ Ahi, const __nv_bfloat16* __restrict__ Alo,
    const __nv_bfloat16* __restrict__ Bhi, const __nv_bfloat16* __restrict__ Blo,
    int row0, int col0, int kc)
{
    #pragma unroll
    for (int it = 0; it < 2; it++) {
        const int u = tid + it * 256;          // 0..511
        const int r = u >> 2;
        const int j = u & 3;
        const uint32_t off = (uint32_t)(r * 80 + j * 16);
        const size_t ga = (size_t)(row0 + r) * HID + kc * 32 + j * 8;
        const size_t gb = (size_t)(col0 + r) * HID + kc * 32 + j * 8;
        cpa16(sb + 0 * GMAT + off, Ahi + ga);
        cpa16(sb + 1 * GMAT + off, Alo + ga);
        cpa16(sb + 2 * GMAT + off, Bhi + gb);
        cpa16(sb + 3 * GMAT + off, Blo + gb);
    }
}

__global__ __launch_bounds__(256) void gemm_mma_kernel(
    const __nv_bfloat16* __restrict__ Ahi, const __nv_bfloat16* __restrict__ Alo,
    const __nv_bfloat16* __restrict__ Bhi, const __nv_bfloat16* __restrict__ Blo,
    const float* __restrict__ bias, float* __restrict__ Cf,
    __nv_bfloat16* __restrict__ Chi, __nv_bfloat16* __restrict__ Clo,
    int N, int mode)
{
    extern __shared__ __align__(128) char smem[];
    const int tid = threadIdx.x;
    const int lane = tid & 31;
    const int wid = tid >> 5;
    const int wr = wid & 3;        // m direction (4)
    const int wc = wid >> 2;       // n direction (2)
    const int row0 = blockIdx.y * 128;
    const int col0 = blockIdx.x * 128;
    const uint32_t sb = smem_u32(smem);

    g_load_stage(sb, tid, Ahi, Alo, Bhi, Blo, row0, col0, 0);
    CP_COMMIT();
    g_load_stage(sb + GSTAGE, tid, Ahi, Alo, Bhi, Blo, row0, col0, 1);
    CP_COMMIT();

    float acc[2][8][4];
    #pragma unroll
    for (int mt = 0; mt < 2; mt++)
        #pragma unroll
        for (int nt = 0; nt < 8; nt++)
            #pragma unroll
            for (int q = 0; q < 4; q++) acc[mt][nt][q] = 0.0f;

    for (int i = 0; i < GNCH; i++) {
        if (i >= GNCH - 2) CP_WAIT0(); else CP_WAIT1();
        __syncthreads();
        const uint32_t st = sb + (i & 1) * GSTAGE;

        #pragma unroll
        for (int ks = 0; ks < 2; ks++) {
            // A fragments (hi, lo) for 2 m-tiles
            uint32_t af[2][2][4];
            #pragma unroll
            for (int mt = 0; mt < 2; mt++) {
                const uint32_t r = wr * 32 + mt * 16 + (lane & 15);
                const uint32_t cb = ks * 32 + ((lane >> 4) << 4);
                ldm4(af[0][mt], st + 0 * GMAT + r * 80 + cb);
                ldm4(af[1][mt], st + 1 * GMAT + r * 80 + cb);
            }
            // B fragments (hi, lo) for 8 n-tiles
            uint32_t bfh[8][2], bfl[8][2];
            #pragma unroll
            for (int p = 0; p < 4; p++) {
                const int g = lane >> 3;
                const uint32_t nr = wc * 64 + p * 16 + (lane & 7) + ((g >> 1) << 3);
                const uint32_t cb = ks * 32 + ((g & 1) << 4);
                uint32_t t[4];
                ldm4(t, st + 2 * GMAT + nr * 80 + cb);
                bfh[2 * p][0] = t[0]; bfh[2 * p][1] = t[1];
                bfh[2 * p + 1][0] = t[2]; bfh[2 * p + 1][1] = t[3];
                ldm4(t, st + 3 * GMAT + nr * 80 + cb);
                bfl[2 * p][0] = t[0]; bfl[2 * p][1] = t[1];
                bfl[2 * p + 1][0] = t[2]; bfl[2 * p + 1][1] = t[3];
            }
            #pragma unroll
            for (int mt = 0; mt < 2; mt++)
                #pragma unroll
                for (int nt = 0; nt < 8; nt++) {
                    mma16816(acc[mt][nt], af[0][mt], bfh[nt][0], bfh[nt][1]);
                    mma16816(acc[mt][nt], af[0][mt], bfl[nt][0], bfl[nt][1]);
                    mma16816(acc[mt][nt], af[1][mt], bfh[nt][0], bfh[nt][1]);
                }
        }
        __syncthreads();
        if (i + 2 < GNCH) {
            g_load_stage(sb + (i & 1) * GSTAGE, tid, Ahi, Alo, Bhi, Blo, row0, col0, i + 2);
            CP_COMMIT();
        }
    }

    // Epilogue
    #pragma unroll
    for (int mt = 0; mt < 2; mt++) {
        const int r = row0 + wr * 32 + mt * 16 + (lane >> 2);
        #pragma unroll
        for (int nt = 0; nt < 8; nt++) {
            const int c = col0 + wc * 64 + nt * 8 + (lane & 3) * 2;
            const float b0 = bias[c], b1 = bias[c + 1];
            const float v0 = acc[mt][nt][0] + b0, v1 = acc[mt][nt][1] + b1;
            const float v2 = acc[mt][nt][2] + b0, v3 = acc[mt][nt][3] + b1;
            if (mode == 0) {
                *(float2*)&Cf[(size_t)r * N + c]       = make_float2(v0, v1);
                *(float2*)&Cf[(size_t)(r + 8) * N + c] = make_float2(v2, v3);
            } else {
                __nv_bfloat16 h0, h1, h2, h3, l0, l1, l2, l3;
                split1(v0, h0, l0); split1(v1, h1, l1);
                split1(v2, h2, l2); split1(v3, h3, l3);
                *(uint32_t*)&Chi[(size_t)r * N + c]       = pack2(h0, h1);
                *(uint32_t*)&Clo[(size_t)r * N + c]       = pack2(l0, l1);
                *(uint32_t*)&Chi[(size_t)(r + 8) * N + c] = pack2(h2, h3);
                *(uint32_t*)&Clo[(size_t)(r + 8) * N + c] = pack2(l2, l3);
            }
        }
    }
}

// ---------------------------------------------------------------------------
// Flash attention (causal) with mma.sync split-bf16.
// 64x64 tiles, 4 warps (128 threads). Q frags hoisted. K/V double-buffered.
// Softmax in C-fragment registers; P packed directly to A fragments.
// Outputs split bf16 hi/lo for the proj GEMM.
// Smem rows: 128B + XOR-16B swizzle.
// ---------------------------------------------------------------------------
#define FQH 0
#define FQL 8192
#define FST 16384
#define FSTAGE 32768               // Kh|Kl|Vh|Vl each 8192
#define FSMEM (FST + 2 * FSTAGE)   // 81920

__device__ __forceinline__ uint32_t fsw(int r, int j) {
    return (uint32_t)(r * 128 + ((j ^ (r & 7)) << 4));
}

__device__ __forceinline__ void f_load_kv(
    uint32_t sb, int tid,
    const __nv_bfloat16* __restrict__ qh, const __nv_bfloat16* __restrict__ ql,
    int b, int h, int k0)
{
    #pragma unroll
    for (int it = 0; it < 4; it++) {
        const int u = tid + it * 128;      // 0..511
        const int r = u >> 3;
        const int j = u & 7;
        const uint32_t off = fsw(r, j);
        const size_t gk = (size_t)(b * SEQ + k0 + r) * (3 * HID) + HID + h * DHEAD + j * 8;
        const size_t gv = gk + HID;
        cpa16(sb + 0     + off, qh + gk);
        cpa16(sb + 8192  + off, ql + gk);
        cpa16(sb + 16384 + off, qh + gv);
        cpa16(sb + 24576 + off, ql + gv);
    }
}

__global__ __launch_bounds__(128) void flash_mma_kernel(
    const __nv_bfloat16* __restrict__ qh, const __nv_bfloat16* __restrict__ ql,
    __nv_bfloat16* __restrict__ Ohi, __nv_bfloat16* __restrict__ Olo)
{
    extern __shared__ __align__(128) char smem[];
    const int tid = threadIdx.x;
    const int lane = tid & 31;
    const int wr = tid >> 5;               // warp id: 16-row band
    const int bh = blockIdx.y;
    const int b = bh >> 4;
    const int h = bh & 15;
    const int q0 = blockIdx.x * 64;
    const uint32_t sb = smem_u32(smem);
    const int ktiles = q0 / 64 + 1;

    // Prologue: Q + stage0 (one group), stage1 (second group)
    #pragma unroll
    for (int it = 0; it < 4; it++) {
        const int u = tid + it * 128;
        const int r = u >> 3;
        const int j = u & 7;
        const uint32_t off = fsw(r, j);
        const size_t gq = (size_t)(b * SEQ + q0 + r) * (3 * HID) + h * DHEAD + j * 8;
        cpa16(sb + FQH + off, qh + gq);
        cpa16(sb + FQL + off, ql + gq);
    }
    f_load_kv(sb + FST, tid, qh, ql, b, h, 0);
    CP_COMMIT();
    if (ktiles > 1) {
        f_load_kv(sb + FST + FSTAGE, tid, qh, ql, b, h, 64);
        CP_COMMIT();
    }

    uint32_t qf[2][4][4];                  // [hi/lo][kstep][4]
    float m0 = -INFINITY, m1 = -INFINITY, l0 = 0.0f, l1 = 0.0f;
    float acc[8][4];
    #pragma unroll
    for (int nt = 0; nt < 8; nt++)
        #pragma unroll
        for (int q = 0; q < 4; q++) acc[nt][q] = 0.0f;

    const int qr0 = q0 + wr * 16 + (lane >> 2);
    const int qr1 = qr0 + 8;

    for (int kt = 0; kt < ktiles; kt++) {
        if (kt >= ktiles - 2) CP_WAIT0(); else CP_WAIT1();
        __syncthreads();
        const uint32_t st = sb + FST + (kt & 1) * FSTAGE;

        if (kt == 0) {
            // Hoist Q fragments (loop-invariant)
            #pragma unroll
            for (int ks = 0; ks < 4; ks++) {
                const int r = wr * 16 + (lane & 15);
                const int j = ks * 2 + (lane >> 4);
                ldm4(qf[0][ks], sb + FQH + fsw(r, j));
                ldm4(qf[1][ks], sb + FQL + fsw(r, j));
            }
        }

        // ---- S = Q @ K^T (3-term split) ----
        float sf[8][4];
        #pragma unroll
        for (int nt = 0; nt < 8; nt++)
            #pragma unroll
            for (int q = 0; q < 4; q++) sf[nt][q] = 0.0f;

        #pragma unroll
        for (int ks = 0; ks < 4; ks++) {
            #pragma unroll
            for (int p = 0; p < 4; p++) {
                const int g = lane >> 3;
                const int nr = p * 16 + (lane & 7) + ((g >> 1) << 3);
                const int j = ks * 2 + (g & 1);
                uint32_t th[4], tl[4];
                ldm4(th, st + 0 + nr * 128 + (((uint32_t)(j ^ (nr & 7))) << 4));
                ldm4(tl, st + 8192 + nr * 128 + (((uint32_t)(j ^ (nr & 7))) << 4));
                mma16816(sf[2 * p],     qf[0][ks], th[0], th[1]);
                mma16816(sf[2 * p],     qf[0][ks], tl[0], tl[1]);
                mma16816(sf[2 * p],     qf[1][ks], th[0], th[1]);
                mma16816(sf[2 * p + 1], qf[0][ks], th[2], th[3]);
                mma16816(sf[2 * p + 1], qf[0][ks], tl[2], tl[3]);
                mma16816(sf[2 * p + 1], qf[1][ks], th[2], th[3]);
            }
        }

        // ---- softmax (scale, mask, online update) ----
        const int k0 = kt * 64;
        #pragma unroll
        for (int nt = 0; nt < 8; nt++)
            #pragma unroll
            for (int q = 0; q < 4; q++) sf[nt][q] *= 0.125f;

        if (kt == ktiles - 1) {  // diagonal tile
            #pragma unroll
            for (int nt = 0; nt < 8; nt++) {
                const int c = k0 + nt * 8 + (lane & 3) * 2;
                if (c > qr0)     sf[nt][0] = -INFINITY;
                if (c + 1 > qr0) sf[nt][1] = -INFINITY;
                if (c > qr1)     sf[nt][2] = -INFINITY;
                if (c + 1 > qr1) sf[nt][3] = -INFINITY;
            }
        }

        float cm0 = -INFINITY, cm1 = -INFINITY;
        #pragma unroll
        for (int nt = 0; nt < 8; nt++) {
            cm0 = fmaxf(cm0, fmaxf(sf[nt][0], sf[nt][1]));
            cm1 = fmaxf(cm1, fmaxf(sf[nt][2], sf[nt][3]));
        }
        cm0 = fmaxf(cm0, __shfl_xor_sync(0xffffffffu, cm0, 1));
        cm0 = fmaxf(cm0, __shfl_xor_sync(0xffffffffu, cm0, 2));
        cm1 = fmaxf(cm1, __shfl_xor_sync(0xffffffffu, cm1, 1));
        cm1 = fmaxf(cm1, __shfl_xor_sync(0xffffffffu, cm1, 2));

        const float mn0 = fmaxf(m0, cm0);
        const float mn1 = fmaxf(m1, cm1);
        const float al0 = __expf(m0 - mn0);
        const float al1 = __expf(m1 - mn1);
        m0 = mn0; m1 = mn1;

        float rs0 = 0.0f, rs1 = 0.0f;
        #pragma unroll
        for (int nt = 0; nt < 8; nt++) {
            sf[nt][0] = __expf(sf[nt][0] - mn0);
            sf[nt][1] = __expf(sf[nt][1] - mn0);
            sf[nt][2] = __expf(sf[nt][2] - mn1);
            sf[nt][3] = __expf(sf[nt][3] - mn1);
            rs0 += sf[nt][0] + sf[nt][1];
            rs1 += sf[nt][2] + sf[nt][3];
        }
        rs0 += __shfl_xor_sync(0xffffffffu, rs0, 1);
        rs0 += __shfl_xor_sync(0xffffffffu, rs0, 2);
        rs1 += __shfl_xor_sync(0xffffffffu, rs1, 1);
        rs1 += __shfl_xor_sync(0xffffffffu, rs1, 2);
        l0 = l0 * al0 + rs0;
        l1 = l1 * al1 + rs1;

        #pragma unroll
        for (int nt = 0; nt < 8; nt++) {
            acc[nt][0] *= al0; acc[nt][1] *= al0;
            acc[nt][2] *= al1; acc[nt][3] *= al1;
        }

        // ---- pack P into A fragments (hi/lo) ----
        uint32_t ph[4][4], pl[4][4];
        #pragma unroll
        for (int ks = 0; ks < 4; ks++) {
            #pragma unroll
            for (int half = 0; half < 2; half++) {       // half0: regs 0/1, half1: regs 2/3
                const int nta = 2 * ks, ntb = 2 * ks + 1;
                const float pa = sf[half ? ntb : nta][half ? 0 : 0]; // placeholder
                (void)pa;
            }
            __nv_bfloat16 h00, h01, h10, h11, h20, h21, h30, h31;
            __nv_bfloat16 e00, e01, e10, e11, e20, e21, e30, e31;
            split1(sf[2 * ks][0], h00, e00); split1(sf[2 * ks][1], h01, e01);
            split1(sf[2 * ks][2], h10, e10); split1(sf[2 * ks][3], h11, e11);
            split1(sf[2 * ks + 1][0], h20, e20); split1(sf[2 * ks + 1][1], h21, e21);
            split1(sf[2 * ks + 1][2], h30, e30); split1(sf[2 * ks + 1][3], h31, e31);
            ph[ks][0] = pack2(h00, h01); ph[ks][1] = pack2(h10, h11);
            ph[ks][2] = pack2(h20, h21); ph[ks][3] = pack2(h30, h31);
            pl[ks][0] = pack2(e00, e01); pl[ks][1] = pack2(e10, e11);
            pl[ks][2] = pack2(e20, e21); pl[ks][3] = pack2(e30, e31);
        }

        // ---- O += P @ V (3-term split) ----
        #pragma unroll
        for (int ks = 0; ks < 4; ks++) {
            #pragma unroll
            for (int dp = 0; dp < 4; dp++) {
                const int g = lane >> 3;
                const int krow = ks * 16 + (lane & 7) + ((g & 1) << 3);
                const int j = dp * 2 + (g >> 1);
                uint32_t th[4], tl[4];
                ldm4t(th, st + 16384 + krow * 128 + (((uint32_t)(j ^ (krow & 7))) << 4));
                ldm4t(tl, st + 24576 + krow * 128 + (((uint32_t)(j ^ (krow & 7))) << 4));
                mma16816(acc[2 * dp],     ph[ks], th[0], th[1]);
                mma16816(acc[2 * dp],     ph[ks], tl[0], tl[1]);
                mma16816(acc[2 * dp],     pl[ks], th[0], th[1]);
                mma16816(acc[2 * dp + 1], ph[ks], th[2], th[3]);
                mma16816(acc[2 * dp + 1], ph[ks], tl[2], tl[3]);
                mma16816(acc[2 * dp + 1], pl[ks], th[2], th[3]);
            }
        }

        __syncthreads();
        if (kt + 2 < ktiles) {
            f_load_kv(sb + FST + (kt & 1) * FSTAGE, tid, qh, ql, b, h, (kt + 2) * 64);
            CP_COMMIT();
        }
    }

    // Epilogue: normalize, split to bf16 hi/lo
    const float i0 = 1.0f / l0;
    const float i1 = 1.0f / l1;
    #pragma unroll
    for (int nt = 0; nt < 8; nt++) {
        const int c = h * DHEAD + nt * 8 + (lane & 3) * 2;
        const size_t o0 = (size_t)(b * SEQ + qr0) * HID + c;
        const size_t o1 = (size_t)(b * SEQ + qr1) * HID + c;
        __nv_bfloat16 h0, h1, h2, h3, e0, e1, e2, e3;
        split1(acc[nt][0] * i0, h0, e0);
        split1(acc[nt][1] * i0, h1, e1);
        split1(acc[nt][2] * i1, h2, e2);
        split1(acc[nt][3] * i1, h3, e3);
        *(uint32_t*)&Ohi[o0] = pack2(h0, h1);
        *(uint32_t*)&Olo[o0] = pack2(e0, e1);
        *(uint32_t*)&Ohi[o1] = pack2(h2, h3);
        *(uint32_t*)&Olo[o1] = pack2(e2, e3);
    }
}

// ---------------------------------------------------------------------------
// Launch
// ---------------------------------------------------------------------------
extern "C" void kernel_launch(void* const* d_in, const int* in_sizes, int n_in,
                              void* d_out, int out_size)
{
    const float* x      = (const float*)d_in[0];   // [B,S,H]
    const float* w_attn = (const float*)d_in[1];   // [H, 3H]
    const float* b_attn = (const float*)d_in[2];   // [3H]
    const float* w_proj = (const float*)d_in[3];   // [H, H]
    const float* b_proj = (const float*)d_in[4];   // [H]
    float* out = (float*)d_out;                    // [B,S,H]

    __nv_bfloat16 *xhi, *xlo, *qkvh, *qkvl, *ahi, *alo, *wahi, *walo, *wphi, *wplo;
    cudaGetSymbolAddress((void**)&xhi,  g_xhi);
    cudaGetSymbolAddress((void**)&xlo,  g_xlo);
    cudaGetSymbolAddress((void**)&qkvh, g_qkvh);
    cudaGetSymbolAddress((void**)&qkvl, g_qkvl);
    cudaGetSymbolAddress((void**)&ahi,  g_ahi);
    cudaGetSymbolAddress((void**)&alo,  g_alo);
    cudaGetSymbolAddress((void**)&wahi, g_wahi);
    cudaGetSymbolAddress((void**)&walo, g_walo);
    cudaGetSymbolAddress((void**)&wphi, g_wphi);
    cudaGetSymbolAddress((void**)&wplo, g_wplo);

    cudaFuncSetAttribute(gemm_mma_kernel,
                         cudaFuncAttributeMaxDynamicSharedMemorySize, GSMEM);
    cudaFuncSetAttribute(flash_mma_kernel,
                         cudaFuncAttributeMaxDynamicSharedMemorySize, FSMEM);

    // 0) Conversions
    {
        const int n4 = MTOT * HID / 4;
        split_kernel<<<n4 / 256, 256>>>(x, xhi, xlo, n4);
        tsplit_kernel<<<dim3(3 * HID / 32, HID / 32), 256>>>(w_attn, wahi, walo, HID, 3 * HID);
        tsplit_kernel<<<dim3(HID / 32, HID / 32), 256>>>(w_proj, wphi, wplo, HID, HID);
    }

    // 1) QKV projection -> split bf16 output
    gemm_mma_kernel<<<dim3(3 * HID / 128, MTOT / 128), 256, GSMEM>>>(
        xhi, xlo, wahi, walo, b_attn, nullptr, qkvh, qkvl, 3 * HID, 1);

    // 2) Flash attention -> split bf16 output
    flash_mma_kernel<<<dim3(SEQ / 64, BATCH * NHEAD), 128, FSMEM>>>(
        qkvh, qkvl, ahi, alo);

    // 3) Output projection -> fp32
    gemm_mma_kernel<<<dim3(HID / 128, MTOT / 128), 256, GSMEM>>>(
        ahi, alo, wphi, wplo, b_proj, out, nullptr, nullptr, HID, 0);
}

// round 4
// speedup vs baseline: 3.3117x; 1.0937x over previous
#include <cuda_runtime.h>
#include <cuda_bf16.h>
#include <math.h>
#include <stdint.h>
#include <string.h>

// Problem constants
#define BATCH 2
#define SEQ   2048
#define HID   1024
#define NHEAD 16
#define DHEAD 64
#define MTOT  (BATCH * SEQ)        // 4096 rows

// ---------------------------------------------------------------------------
// Scratch (device globals: allocation-free per harness rules)
// ---------------------------------------------------------------------------
__device__ __nv_bfloat16 g_xhi[(size_t)MTOT * HID];
__device__ __nv_bfloat16 g_xlo[(size_t)MTOT * HID];
__device__ __nv_bfloat16 g_qkvh[(size_t)MTOT * 3 * HID];
__device__ __nv_bfloat16 g_qkvl[(size_t)MTOT * 3 * HID];
__device__ __nv_bfloat16 g_ahi[(size_t)MTOT * HID];
__device__ __nv_bfloat16 g_alo[(size_t)MTOT * HID];
__device__ __nv_bfloat16 g_wahi[(size_t)3 * HID * HID];   // [3H, H] transposed
__device__ __nv_bfloat16 g_walo[(size_t)3 * HID * HID];
__device__ __nv_bfloat16 g_wphi[(size_t)HID * HID];       // [H, H] transposed
__device__ __nv_bfloat16 g_wplo[(size_t)HID * HID];

// ---------------------------------------------------------------------------
// Helpers
// ---------------------------------------------------------------------------
__device__ __forceinline__ uint32_t smem_u32(const void* p) {
    uint32_t a;
    asm("{ .reg .u64 t; cvta.to.shared.u64 t, %1; cvt.u32.u64 %0, t; }" : "=r"(a) : "l"(p));
    return a;
}

__device__ __forceinline__ void cpa16(uint32_t dst, const void* src) {
    asm volatile("cp.async.cg.shared.global [%0], [%1], 16;" :: "r"(dst), "l"(src));
}
#define CP_COMMIT() asm volatile("cp.async.commit_group;" ::: "memory")
#define CP_WAIT0()  asm volatile("cp.async.wait_group 0;" ::: "memory")
#define CP_WAIT1()  asm volatile("cp.async.wait_group 1;" ::: "memory")

__device__ __forceinline__ void ldm4(uint32_t* r, uint32_t a) {
    asm volatile("ldmatrix.sync.aligned.m8n8.x4.shared.b16 {%0,%1,%2,%3}, [%4];"
                 : "=r"(r[0]), "=r"(r[1]), "=r"(r[2]), "=r"(r[3]) : "r"(a));
}
__device__ __forceinline__ void ldm4t(uint32_t* r, uint32_t a) {
    asm volatile("ldmatrix.sync.aligned.m8n8.x4.trans.shared.b16 {%0,%1,%2,%3}, [%4];"
                 : "=r"(r[0]), "=r"(r[1]), "=r"(r[2]), "=r"(r[3]) : "r"(a));
}

// D(+=): m16n8k16 row.col bf16 -> f32
__device__ __forceinline__ void mma16816(float* d, const uint32_t* a, uint32_t b0, uint32_t b1) {
    asm volatile(
        "mma.sync.aligned.m16n8k16.row.col.f32.bf16.bf16.f32 "
        "{%0,%1,%2,%3}, {%4,%5,%6,%7}, {%8,%9}, {%0,%1,%2,%3};"
        : "+f"(d[0]), "+f"(d[1]), "+f"(d[2]), "+f"(d[3])
        : "r"(a[0]), "r"(a[1]), "r"(a[2]), "r"(a[3]), "r"(b0), "r"(b1));
}

__device__ __forceinline__ uint32_t pack2(__nv_bfloat16 lo, __nv_bfloat16 hi) {
    union { __nv_bfloat162 v; uint32_t u; } c;
    c.v.x = lo; c.v.y = hi;
    return c.u;
}

__device__ __forceinline__ void split1(float v, __nv_bfloat16& h, __nv_bfloat16& l) {
    h = __float2bfloat16(v);
    l = __float2bfloat16(v - __bfloat162float(h));
}

// ---------------------------------------------------------------------------
// Conversion kernels
// ---------------------------------------------------------------------------
__global__ __launch_bounds__(256) void split_kernel(
    const float* __restrict__ in, __nv_bfloat16* __restrict__ hi,
    __nv_bfloat16* __restrict__ lo, int n4)
{
    int i = blockIdx.x * blockDim.x + threadIdx.x;
    if (i >= n4) return;
    float4 v = ((const float4*)in)[i];
    __nv_bfloat16 h0, h1, h2, h3, l0, l1, l2, l3;
    split1(v.x, h0, l0); split1(v.y, h1, l1); split1(v.z, h2, l2); split1(v.w, h3, l3);
    ((uint32_t*)hi)[i * 2]     = pack2(h0, h1);
    ((uint32_t*)hi)[i * 2 + 1] = pack2(h2, h3);
    ((uint32_t*)lo)[i * 2]     = pack2(l0, l1);
    ((uint32_t*)lo)[i * 2 + 1] = pack2(l2, l3);
}

// in: [K_, N_] fp32 row-major -> out hi/lo: [N_, K_] bf16 row-major
__global__ __launch_bounds__(256) void tsplit_kernel(
    const float* __restrict__ in, __nv_bfloat16* __restrict__ hi,
    __nv_bfloat16* __restrict__ lo, int K_, int N_)
{
    __shared__ float t[32][33];
    const int n0 = blockIdx.x * 32;
    const int k0 = blockIdx.y * 32;
    const int tx = threadIdx.x & 31;
    const int ty = threadIdx.x >> 5;
    #pragma unroll
    for (int i = 0; i < 32; i += 8)
        t[ty + i][tx] = in[(size_t)(k0 + ty + i) * N_ + n0 + tx];
    __syncthreads();
    #pragma unroll
    for (int i = 0; i < 32; i += 8) {
        float v = t[tx][ty + i];
        __nv_bfloat16 h, l;
        split1(v, h, l);
        const size_t o = (size_t)(n0 + ty + i) * K_ + k0 + tx;
        hi[o] = h;
        lo[o] = l;
    }
}

// ---------------------------------------------------------------------------
// mma.sync split-bf16 GEMM: C[M,N] = A[M,K]@B[K,N] + bias
// A hi/lo [M,K]; B hi/lo transposed [N,K]. M=4096, K=1024.
// 128x128 CTA tile, BK=32, 8 warps (4x2), warp tile 32x64.
// __launch_bounds__(256, 2): cap regs at 128 so 2 CTAs fit per SM -> barrier
// and epilogue latency of one CTA hidden behind the other's MMA work.
// ---------------------------------------------------------------------------
#define GMAT 10240                 // 128 rows * 80B
#define GSTAGE (4 * GMAT)          // Ah|Al|Bh|Bl = 40960
#define GSMEM (2 * GSTAGE)         // 81920
#define GNCH (HID / 32)            // 32 k-chunks

__device__ __forceinline__ void g_load_stage(
    uint32_t sb, int tid,
    const __nv_bfloat16* __restrict__ Ahi, const __nv_bfloat16* __restrict__ Alo,
    const __nv_bfloat16* __restrict__ Bhi, const __nv_bfloat16* __restrict__ Blo,
    int row0, int col0, int kc)
{
    #pragma unroll
    for (int it = 0; it < 2; it++) {
        const int u = tid + it * 256;          // 0..511
        const int r = u >> 2;
        const int j = u & 3;
        const uint32_t off = (uint32_t)(r * 80 + j * 16);
        const size_t ga = (size_t)(row0 + r) * HID + kc * 32 + j * 8;
        const size_t gb = (size_t)(col0 + r) * HID + kc * 32 + j * 8;
        cpa16(sb + 0 * GMAT + off, Ahi + ga);
        cpa16(sb + 1 * GMAT + off, Alo + ga);
        cpa16(sb + 2 * GMAT + off, Bhi + gb);
        cpa16(sb + 3 * GMAT + off, Blo + gb);
    }
}

__global__ __launch_bounds__(256, 2) void gemm_mma_kernel(
    const __nv_bfloat16* __restrict__ Ahi, const __nv_bfloat16* __restrict__ Alo,
    const __nv_bfloat16* __restrict__ Bhi, const __nv_bfloat16* __restrict__ Blo,
    const float* __restrict__ bias, float* __restrict__ Cf,
    __nv_bfloat16* __restrict__ Chi, __nv_bfloat16* __restrict__ Clo,
    int N, int mode)
{
    extern __shared__ __align__(128) char smem[];
    const int tid = threadIdx.x;
    const int lane = tid & 31;
    const int wid = tid >> 5;
    const int wr = wid & 3;        // m direction (4)
    const int wc = wid >> 2;       // n direction (2)
    const int row0 = blockIdx.y * 128;
    const int col0 = blockIdx.x * 128;
    const uint32_t sb = smem_u32(smem);

    g_load_stage(sb, tid, Ahi, Alo, Bhi, Blo, row0, col0, 0);
    CP_COMMIT();
    g_load_stage(sb + GSTAGE, tid, Ahi, Alo, Bhi, Blo, row0, col0, 1);
    CP_COMMIT();

    float acc[2][8][4];
    #pragma unroll
    for (int mt = 0; mt < 2; mt++)
        #pragma unroll
        for (int nt = 0; nt < 8; nt++)
            #pragma unroll
            for (int q = 0; q < 4; q++) acc[mt][nt][q] = 0.0f;

    for (int i = 0; i < GNCH; i++) {
        if (i >= GNCH - 2) CP_WAIT0(); else CP_WAIT1();
        __syncthreads();
        const uint32_t st = sb + (i & 1) * GSTAGE;

        #pragma unroll
        for (int ks = 0; ks < 2; ks++) {
            // A fragments (hi, lo) for 2 m-tiles
            uint32_t af[2][2][4];
            #pragma unroll
            for (int mt = 0; mt < 2; mt++) {
                const uint32_t r = wr * 32 + mt * 16 + (lane & 15);
                const uint32_t cb = ks * 32 + ((lane >> 4) << 4);
                ldm4(af[0][mt], st + 0 * GMAT + r * 80 + cb);
                ldm4(af[1][mt], st + 1 * GMAT + r * 80 + cb);
            }
            // B fragments (hi, lo) for 8 n-tiles
            uint32_t bfh[8][2], bfl[8][2];
            #pragma unroll
            for (int p = 0; p < 4; p++) {
                const int g = lane >> 3;
                const uint32_t nr = wc * 64 + p * 16 + (lane & 7) + ((g >> 1) << 3);
                const uint32_t cb = ks * 32 + ((g & 1) << 4);
                uint32_t t[4];
                ldm4(t, st + 2 * GMAT + nr * 80 + cb);
                bfh[2 * p][0] = t[0]; bfh[2 * p][1] = t[1];
                bfh[2 * p + 1][0] = t[2]; bfh[2 * p + 1][1] = t[3];
                ldm4(t, st + 3 * GMAT + nr * 80 + cb);
                bfl[2 * p][0] = t[0]; bfl[2 * p][1] = t[1];
                bfl[2 * p + 1][0] = t[2]; bfl[2 * p + 1][1] = t[3];
            }
            #pragma unroll
            for (int mt = 0; mt < 2; mt++)
                #pragma unroll
                for (int nt = 0; nt < 8; nt++) {
                    mma16816(acc[mt][nt], af[0][mt], bfh[nt][0], bfh[nt][1]);
                    mma16816(acc[mt][nt], af[0][mt], bfl[nt][0], bfl[nt][1]);
                    mma16816(acc[mt][nt], af[1][mt], bfh[nt][0], bfh[nt][1]);
                }
        }
        __syncthreads();
        if (i + 2 < GNCH) {
            g_load_stage(sb + (i & 1) * GSTAGE, tid, Ahi, Alo, Bhi, Blo, row0, col0, i + 2);
            CP_COMMIT();
        }
    }

    // Epilogue
    #pragma unroll
    for (int mt = 0; mt < 2; mt++) {
        const int r = row0 + wr * 32 + mt * 16 + (lane >> 2);
        #pragma unroll
        for (int nt = 0; nt < 8; nt++) {
            const int c = col0 + wc * 64 + nt * 8 + (lane & 3) * 2;
            const float b0 = bias[c], b1 = bias[c + 1];
            const float v0 = acc[mt][nt][0] + b0, v1 = acc[mt][nt][1] + b1;
            const float v2 = acc[mt][nt][2] + b0, v3 = acc[mt][nt][3] + b1;
            if (mode == 0) {
                *(float2*)&Cf[(size_t)r * N + c]       = make_float2(v0, v1);
                *(float2*)&Cf[(size_t)(r + 8) * N + c] = make_float2(v2, v3);
            } else {
                __nv_bfloat16 h0, h1, h2, h3, l0, l1, l2, l3;
                split1(v0, h0, l0); split1(v1, h1, l1);
                split1(v2, h2, l2); split1(v3, h3, l3);
                *(uint32_t*)&Chi[(size_t)r * N + c]       = pack2(h0, h1);
                *(uint32_t*)&Clo[(size_t)r * N + c]       = pack2(l0, l1);
                *(uint32_t*)&Chi[(size_t)(r + 8) * N + c] = pack2(h2, h3);
                *(uint32_t*)&Clo[(size_t)(r + 8) * N + c] = pack2(l2, l3);
            }
        }
    }
}

// ---------------------------------------------------------------------------
// Flash attention (causal) with mma.sync split-bf16.
// 64x64 tiles, 4 warps (128 threads). Q frags hoisted. K/V double-buffered.
// Softmax in C-fragment registers; P packed directly to A fragments.
// Outputs split bf16 hi/lo for the proj GEMM.
// ---------------------------------------------------------------------------
#define FQH 0
#define FQL 8192
#define FST 16384
#define FSTAGE 32768               // Kh|Kl|Vh|Vl each 8192
#define FSMEM (FST + 2 * FSTAGE)   // 81920

__device__ __forceinline__ uint32_t fsw(int r, int j) {
    return (uint32_t)(r * 128 + ((j ^ (r & 7)) << 4));
}

__device__ __forceinline__ void f_load_kv(
    uint32_t sb, int tid,
    const __nv_bfloat16* __restrict__ qh, const __nv_bfloat16* __restrict__ ql,
    int b, int h, int k0)
{
    #pragma unroll
    for (int it = 0; it < 4; it++) {
        const int u = tid + it * 128;      // 0..511
        const int r = u >> 3;
        const int j = u & 7;
        const uint32_t off = fsw(r, j);
        const size_t gk = (size_t)(b * SEQ + k0 + r) * (3 * HID) + HID + h * DHEAD + j * 8;
        const size_t gv = gk + HID;
        cpa16(sb + 0     + off, qh + gk);
        cpa16(sb + 8192  + off, ql + gk);
        cpa16(sb + 16384 + off, qh + gv);
        cpa16(sb + 24576 + off, ql + gv);
    }
}

__global__ __launch_bounds__(128) void flash_mma_kernel(
    const __nv_bfloat16* __restrict__ qh, const __nv_bfloat16* __restrict__ ql,
    __nv_bfloat16* __restrict__ Ohi, __nv_bfloat16* __restrict__ Olo)
{
    extern __shared__ __align__(128) char smem[];
    const int tid = threadIdx.x;
    const int lane = tid & 31;
    const int wr = tid >> 5;               // warp id: 16-row band
    const int bh = blockIdx.y;
    const int b = bh >> 4;
    const int h = bh & 15;
    const int q0 = blockIdx.x * 64;
    const uint32_t sb = smem_u32(smem);
    const int ktiles = q0 / 64 + 1;

    // Prologue: Q + stage0, stage1
    #pragma unroll
    for (int it = 0; it < 4; it++) {
        const int u = tid + it * 128;
        const int r = u >> 3;
        const int j = u & 7;
        const uint32_t off = fsw(r, j);
        const size_t gq = (size_t)(b * SEQ + q0 + r) * (3 * HID) + h * DHEAD + j * 8;
        cpa16(sb + FQH + off, qh + gq);
        cpa16(sb + FQL + off, ql + gq);
    }
    f_load_kv(sb + FST, tid, qh, ql, b, h, 0);
    CP_COMMIT();
    if (ktiles > 1) {
        f_load_kv(sb + FST + FSTAGE, tid, qh, ql, b, h, 64);
        CP_COMMIT();
    }

    uint32_t qf[2][4][4];                  // [hi/lo][kstep][4]
    float m0 = -INFINITY, m1 = -INFINITY, l0 = 0.0f, l1 = 0.0f;
    float acc[8][4];
    #pragma unroll
    for (int nt = 0; nt < 8; nt++)
        #pragma unroll
        for (int q = 0; q < 4; q++) acc[nt][q] = 0.0f;

    const int qr0 = q0 + wr * 16 + (lane >> 2);
    const int qr1 = qr0 + 8;

    for (int kt = 0; kt < ktiles; kt++) {
        if (kt >= ktiles - 2) CP_WAIT0(); else CP_WAIT1();
        __syncthreads();
        const uint32_t st = sb + FST + (kt & 1) * FSTAGE;

        if (kt == 0) {
            // Hoist Q fragments (loop-invariant)
            #pragma unroll
            for (int ks = 0; ks < 4; ks++) {
                const int r = wr * 16 + (lane & 15);
                const int j = ks * 2 + (lane >> 4);
                ldm4(qf[0][ks], sb + FQH + fsw(r, j));
                ldm4(qf[1][ks], sb + FQL + fsw(r, j));
            }
        }

        // ---- S = Q @ K^T (3-term split) ----
        float sf[8][4];
        #pragma unroll
        for (int nt = 0; nt < 8; nt++)
            #pragma unroll
            for (int q = 0; q < 4; q++) sf[nt][q] = 0.0f;

        #pragma unroll
        for (int ks = 0; ks < 4; ks++) {
            #pragma unroll
            for (int p = 0; p < 4; p++) {
                const int g = lane >> 3;
                const int nr = p * 16 + (lane & 7) + ((g >> 1) << 3);
                const int j = ks * 2 + (g & 1);
                uint32_t th[4], tl[4];
                ldm4(th, st + 0 + nr * 128 + (((uint32_t)(j ^ (nr & 7))) << 4));
                ldm4(tl, st + 8192 + nr * 128 + (((uint32_t)(j ^ (nr & 7))) << 4));
                mma16816(sf[2 * p],     qf[0][ks], th[0], th[1]);
                mma16816(sf[2 * p],     qf[0][ks], tl[0], tl[1]);
                mma16816(sf[2 * p],     qf[1][ks], th[0], th[1]);
                mma16816(sf[2 * p + 1], qf[0][ks], th[2], th[3]);
                mma16816(sf[2 * p + 1], qf[0][ks], tl[2], tl[3]);
                mma16816(sf[2 * p + 1], qf[1][ks], th[2], th[3]);
            }
        }

        // ---- softmax (scale, mask, online update) ----
        const int k0 = kt * 64;
        #pragma unroll
        for (int nt = 0; nt < 8; nt++)
            #pragma unroll
            for (int q = 0; q < 4; q++) sf[nt][q] *= 0.125f;

        if (kt == ktiles - 1) {  // diagonal tile
            #pragma unroll
            for (int nt = 0; nt < 8; nt++) {
                const int c = k0 + nt * 8 + (lane & 3) * 2;
                if (c > qr0)     sf[nt][0] = -INFINITY;
                if (c + 1 > qr0) sf[nt][1] = -INFINITY;
                if (c > qr1)     sf[nt][2] = -INFINITY;
                if (c + 1 > qr1) sf[nt][3] = -INFINITY;
            }
        }

        float cm0 = -INFINITY, cm1 = -INFINITY;
        #pragma unroll
        for (int nt = 0; nt < 8; nt++) {
            cm0 = fmaxf(cm0, fmaxf(sf[nt][0], sf[nt][1]));
            cm1 = fmaxf(cm1, fmaxf(sf[nt][2], sf[nt][3]));
        }
        cm0 = fmaxf(cm0, __shfl_xor_sync(0xffffffffu, cm0, 1));
        cm0 = fmaxf(cm0, __shfl_xor_sync(0xffffffffu, cm0, 2));
        cm1 = fmaxf(cm1, __shfl_xor_sync(0xffffffffu, cm1, 1));
        cm1 = fmaxf(cm1, __shfl_xor_sync(0xffffffffu, cm1, 2));

        const float mn0 = fmaxf(m0, cm0);
        const float mn1 = fmaxf(m1, cm1);
        const float al0 = __expf(m0 - mn0);
        const float al1 = __expf(m1 - mn1);
        m0 = mn0; m1 = mn1;

        float rs0 = 0.0f, rs1 = 0.0f;
        #pragma unroll
        for (int nt = 0; nt < 8; nt++) {
            sf[nt][0] = __expf(sf[nt][0] - mn0);
            sf[nt][1] = __expf(sf[nt][1] - mn0);
            sf[nt][2] = __expf(sf[nt][2] - mn1);
            sf[nt][3] = __expf(sf[nt][3] - mn1);
            rs0 += sf[nt][0] + sf[nt][1];
            rs1 += sf[nt][2] + sf[nt][3];
        }
        rs0 += __shfl_xor_sync(0xffffffffu, rs0, 1);
        rs0 += __shfl_xor_sync(0xffffffffu, rs0, 2);
        rs1 += __shfl_xor_sync(0xffffffffu, rs1, 1);
        rs1 += __shfl_xor_sync(0xffffffffu, rs1, 2);
        l0 = l0 * al0 + rs0;
        l1 = l1 * al1 + rs1;

        #pragma unroll
        for (int nt = 0; nt < 8; nt++) {
            acc[nt][0] *= al0; acc[nt][1] *= al0;
            acc[nt][2] *= al1; acc[nt][3] *= al1;
        }

        // ---- pack P into A fragments (hi/lo) ----
        uint32_t ph[4][4], pl[4][4];
        #pragma unroll
        for (int ks = 0; ks < 4; ks++) {
            __nv_bfloat16 h00, h01, h10, h11, h20, h21, h30, h31;
            __nv_bfloat16 e00, e01, e10, e11, e20, e21, e30, e31;
            split1(sf[2 * ks][0], h00, e00); split1(sf[2 * ks][1], h01, e01);
            split1(sf[2 * ks][2], h10, e10); split1(sf[2 * ks][3], h11, e11);
            split1(sf[2 * ks + 1][0], h20, e20); split1(sf[2 * ks + 1][1], h21, e21);
            split1(sf[2 * ks + 1][2], h30, e30); split1(sf[2 * ks + 1][3], h31, e31);
            ph[ks][0] = pack2(h00, h01); ph[ks][1] = pack2(h10, h11);
            ph[ks][2] = pack2(h20, h21); ph[ks][3] = pack2(h30, h31);
            pl[ks][0] = pack2(e00, e01); pl[ks][1] = pack2(e10, e11);
            pl[ks][2] = pack2(e20, e21); pl[ks][3] = pack2(e30, e31);
        }

        // ---- O += P @ V (3-term split) ----
        #pragma unroll
        for (int ks = 0; ks < 4; ks++) {
            #pragma unroll
            for (int dp = 0; dp < 4; dp++) {
                const int g = lane >> 3;
                const int krow = ks * 16 + (lane & 7) + ((g & 1) << 3);
                const int j = dp * 2 + (g >> 1);
                uint32_t th[4], tl[4];
                ldm4t(th, st + 16384 + krow * 128 + (((uint32_t)(j ^ (krow & 7))) << 4));
                ldm4t(tl, st + 24576 + krow * 128 + (((uint32_t)(j ^ (krow & 7))) << 4));
                mma16816(acc[2 * dp],     ph[ks], th[0], th[1]);
                mma16816(acc[2 * dp],     ph[ks], tl[0], tl[1]);
                mma16816(acc[2 * dp],     pl[ks], th[0], th[1]);
                mma16816(acc[2 * dp + 1], ph[ks], th[2], th[3]);
                mma16816(acc[2 * dp + 1], ph[ks], tl[2], tl[3]);
                mma16816(acc[2 * dp + 1], pl[ks], th[2], th[3]);
            }
        }

        __syncthreads();
        if (kt + 2 < ktiles) {
            f_load_kv(sb + FST + (kt & 1) * FSTAGE, tid, qh, ql, b, h, (kt + 2) * 64);
            CP_COMMIT();
        }
    }

    // Epilogue: normalize, split to bf16 hi/lo
    const float i0 = 1.0f / l0;
    const float i1 = 1.0f / l1;
    #pragma unroll
    for (int nt = 0; nt < 8; nt++) {
        const int c = h * DHEAD + nt * 8 + (lane & 3) * 2;
        const size_t o0 = (size_t)(b * SEQ + qr0) * HID + c;
        const size_t o1 = (size_t)(b * SEQ + qr1) * HID + c;
        __nv_bfloat16 h0, h1, h2, h3, e0, e1, e2, e3;
        split1(acc[nt][0] * i0, h0, e0);
        split1(acc[nt][1] * i0, h1, e1);
        split1(acc[nt][2] * i1, h2, e2);
        split1(acc[nt][3] * i1, h3, e3);
        *(uint32_t*)&Ohi[o0] = pack2(h0, h1);
        *(uint32_t*)&Olo[o0] = pack2(e0, e1);
        *(uint32_t*)&Ohi[o1] = pack2(h2, h3);
        *(uint32_t*)&Olo[o1] = pack2(e2, e3);
    }
}

// ---------------------------------------------------------------------------
// Launch
// ---------------------------------------------------------------------------
extern "C" void kernel_launch(void* const* d_in, const int* in_sizes, int n_in,
                              void* d_out, int out_size)
{
    const float* x      = (const float*)d_in[0];   // [B,S,H]
    const float* w_attn = (const float*)d_in[1];   // [H, 3H]
    const float* b_attn = (const float*)d_in[2];   // [3H]
    const float* w_proj = (const float*)d_in[3];   // [H, H]
    const float* b_proj = (const float*)d_in[4];   // [H]
    float* out = (float*)d_out;                    // [B,S,H]

    __nv_bfloat16 *xhi, *xlo, *qkvh, *qkvl, *ahi, *alo, *wahi, *walo, *wphi, *wplo;
    cudaGetSymbolAddress((void**)&xhi,  g_xhi);
    cudaGetSymbolAddress((void**)&xlo,  g_xlo);
    cudaGetSymbolAddress((void**)&qkvh, g_qkvh);
    cudaGetSymbolAddress((void**)&qkvl, g_qkvl);
    cudaGetSymbolAddress((void**)&ahi,  g_ahi);
    cudaGetSymbolAddress((void**)&alo,  g_alo);
    cudaGetSymbolAddress((void**)&wahi, g_wahi);
    cudaGetSymbolAddress((void**)&walo, g_walo);
    cudaGetSymbolAddress((void**)&wphi, g_wphi);
    cudaGetSymbolAddress((void**)&wplo, g_wplo);

    cudaFuncSetAttribute(gemm_mma_kernel,
                         cudaFuncAttributeMaxDynamicSharedMemorySize, GSMEM);
    cudaFuncSetAttribute(flash_mma_kernel,
                         cudaFuncAttributeMaxDynamicSharedMemorySize, FSMEM);

    // 0) Conversions
    {
        const int n4 = MTOT * HID / 4;
        split_kernel<<<n4 / 256, 256>>>(x, xhi, xlo, n4);
        tsplit_kernel<<<dim3(3 * HID / 32, HID / 32), 256>>>(w_attn, wahi, walo, HID, 3 * HID);
        tsplit_kernel<<<dim3(HID / 32, HID / 32), 256>>>(w_proj, wphi, wplo, HID, HID);
    }

    // 1) QKV projection -> split bf16 output
    gemm_mma_kernel<<<dim3(3 * HID / 128, MTOT / 128), 256, GSMEM>>>(
        xhi, xlo, wahi, walo, b_attn, nullptr, qkvh, qkvl, 3 * HID, 1);

    // 2) Flash attention -> split bf16 output
    flash_mma_kernel<<<dim3(SEQ / 64, BATCH * NHEAD), 128, FSMEM>>>(
        qkvh, qkvl, ahi, alo);

    // 3) Output projection -> fp32
    gemm_mma_kernel<<<dim3(HID / 128, MTOT / 128), 256, GSMEM>>>(
        ahi, alo, wphi, wplo, b_proj, out, nullptr, nullptr, HID, 0);
}

// round 6
// speedup vs baseline: 3.8074x; 1.1497x over previous
#include <cuda_runtime.h>
#include <cuda_bf16.h>
#include <math.h>
#include <stdint.h>
#include <string.h>

// Problem constants
#define BATCH 2
#define SEQ   2048
#define HID   1024
#define NHEAD 16
#define DHEAD 64
#define MTOT  (BATCH * SEQ)        // 4096 rows

// ---------------------------------------------------------------------------
// Scratch (device globals: allocation-free per harness rules)
// ---------------------------------------------------------------------------
__device__ __nv_bfloat16 g_xhi[(size_t)MTOT * HID];
__device__ __nv_bfloat16 g_xlo[(size_t)MTOT * HID];
__device__ __nv_bfloat16 g_qkvh[(size_t)MTOT * 3 * HID];
__device__ __nv_bfloat16 g_qkvl[(size_t)MTOT * 3 * HID];
__device__ __nv_bfloat16 g_ahi[(size_t)MTOT * HID];
__device__ __nv_bfloat16 g_alo[(size_t)MTOT * HID];
__device__ __nv_bfloat16 g_wahi[(size_t)3 * HID * HID];   // [3H, H] transposed
__device__ __nv_bfloat16 g_walo[(size_t)3 * HID * HID];
__device__ __nv_bfloat16 g_wphi[(size_t)HID * HID];       // [H, H] transposed
__device__ __nv_bfloat16 g_wplo[(size_t)HID * HID];

// ---------------------------------------------------------------------------
// Helpers
// ---------------------------------------------------------------------------
__device__ __forceinline__ uint32_t smem_u32(const void* p) {
    uint32_t a;
    asm("{ .reg .u64 t; cvta.to.shared.u64 t, %1; cvt.u32.u64 %0, t; }" : "=r"(a) : "l"(p));
    return a;
}

__device__ __forceinline__ void cpa16(uint32_t dst, const void* src) {
    asm volatile("cp.async.cg.shared.global [%0], [%1], 16;" :: "r"(dst), "l"(src));
}
#define CP_COMMIT() asm volatile("cp.async.commit_group;" ::: "memory")
#define CP_WAIT0()  asm volatile("cp.async.wait_group 0;" ::: "memory")
#define CP_WAIT1()  asm volatile("cp.async.wait_group 1;" ::: "memory")

__device__ __forceinline__ void ldm4(uint32_t* r, uint32_t a) {
    asm volatile("ldmatrix.sync.aligned.m8n8.x4.shared.b16 {%0,%1,%2,%3}, [%4];"
                 : "=r"(r[0]), "=r"(r[1]), "=r"(r[2]), "=r"(r[3]) : "r"(a));
}
__device__ __forceinline__ void ldm4t(uint32_t* r, uint32_t a) {
    asm volatile("ldmatrix.sync.aligned.m8n8.x4.trans.shared.b16 {%0,%1,%2,%3}, [%4];"
                 : "=r"(r[0]), "=r"(r[1]), "=r"(r[2]), "=r"(r[3]) : "r"(a));
}

// D(+=): m16n8k16 row.col bf16 -> f32
__device__ __forceinline__ void mma16816(float* d, const uint32_t* a, uint32_t b0, uint32_t b1) {
    asm volatile(
        "mma.sync.aligned.m16n8k16.row.col.f32.bf16.bf16.f32 "
        "{%0,%1,%2,%3}, {%4,%5,%6,%7}, {%8,%9}, {%0,%1,%2,%3};"
        : "+f"(d[0]), "+f"(d[1]), "+f"(d[2]), "+f"(d[3])
        : "r"(a[0]), "r"(a[1]), "r"(a[2]), "r"(a[3]), "r"(b0), "r"(b1));
}

__device__ __forceinline__ uint32_t pack2(__nv_bfloat16 lo, __nv_bfloat16 hi) {
    union { __nv_bfloat162 v; uint32_t u; } c;
    c.v.x = lo; c.v.y = hi;
    return c.u;
}

__device__ __forceinline__ void split1(float v, __nv_bfloat16& h, __nv_bfloat16& l) {
    h = __float2bfloat16(v);
    l = __float2bfloat16(v - __bfloat162float(h));
}

// ---------------------------------------------------------------------------
// Conversion kernels
// ---------------------------------------------------------------------------
__global__ __launch_bounds__(256) void split_kernel(
    const float* __restrict__ in, __nv_bfloat16* __restrict__ hi,
    __nv_bfloat16* __restrict__ lo, int n4)
{
    int i = blockIdx.x * blockDim.x + threadIdx.x;
    if (i >= n4) return;
    float4 v = ((const float4*)in)[i];
    __nv_bfloat16 h0, h1, h2, h3, l0, l1, l2, l3;
    split1(v.x, h0, l0); split1(v.y, h1, l1); split1(v.z, h2, l2); split1(v.w, h3, l3);
    ((uint32_t*)hi)[i * 2]     = pack2(h0, h1);
    ((uint32_t*)hi)[i * 2 + 1] = pack2(h2, h3);
    ((uint32_t*)lo)[i * 2]     = pack2(l0, l1);
    ((uint32_t*)lo)[i * 2 + 1] = pack2(l2, l3);
}

// in: [K_, N_] fp32 row-major -> out hi/lo: [N_, K_] bf16 row-major
__global__ __launch_bounds__(256) void tsplit_kernel(
    const float* __restrict__ in, __nv_bfloat16* __restrict__ hi,
    __nv_bfloat16* __restrict__ lo, int K_, int N_)
{
    __shared__ float t[32][33];
    const int n0 = blockIdx.x * 32;
    const int k0 = blockIdx.y * 32;
    const int tx = threadIdx.x & 31;
    const int ty = threadIdx.x >> 5;
    #pragma unroll
    for (int i = 0; i < 32; i += 8)
        t[ty + i][tx] = in[(size_t)(k0 + ty + i) * N_ + n0 + tx];
    __syncthreads();
    #pragma unroll
    for (int i = 0; i < 32; i += 8) {
        float v = t[tx][ty + i];
        __nv_bfloat16 h, l;
        split1(v, h, l);
        const size_t o = (size_t)(n0 + ty + i) * K_ + k0 + tx;
        hi[o] = h;
        lo[o] = l;
    }
}

// ---------------------------------------------------------------------------
// mma.sync split-bf16 GEMM: C[M,N] = A[M,K]@B[K,N] + bias
// 128x128 CTA tile, BK=32, 8 warps (4x2), warp tile 32x64, 2 CTAs/SM.
// Restructured chunk loop: barrier waits only on LDSM; the second half-chunk's
// MMAs overlap the next prefetch's cp.async issue + DRAM flight.
// ---------------------------------------------------------------------------
#define GMAT 10240                 // 128 rows * 80B
#define GSTAGE (4 * GMAT)          // Ah|Al|Bh|Bl = 40960
#define GSMEM (2 * GSTAGE)         // 81920
#define GNCH (HID / 32)            // 32 k-chunks

__device__ __forceinline__ void g_load_stage(
    uint32_t sb, int tid,
    const __nv_bfloat16* __restrict__ Ahi, const __nv_bfloat16* __restrict__ Alo,
    const __nv_bfloat16* __restrict__ Bhi, const __nv_bfloat16* __restrict__ Blo,
    int row0, int col0, int kc)
{
    #pragma unroll
    for (int it = 0; it < 2; it++) {
        const int u = tid + it * 256;          // 0..511
        const int r = u >> 2;
        const int j = u & 3;
        const uint32_t off = (uint32_t)(r * 80 + j * 16);
        const size_t ga = (size_t)(row0 + r) * HID + kc * 32 + j * 8;
        const size_t gb = (size_t)(col0 + r) * HID + kc * 32 + j * 8;
        cpa16(sb + 0 * GMAT + off, Ahi + ga);
        cpa16(sb + 1 * GMAT + off, Alo + ga);
        cpa16(sb + 2 * GMAT + off, Bhi + gb);
        cpa16(sb + 3 * GMAT + off, Blo + gb);
    }
}

__device__ __forceinline__ void g_load_frags(
    uint32_t st, int ks, int lane, int wr, int wc,
    uint32_t af[2][2][4], uint32_t bfh[8][2], uint32_t bfl[8][2])
{
    #pragma unroll
    for (int mt = 0; mt < 2; mt++) {
        const uint32_t r = wr * 32 + mt * 16 + (lane & 15);
        const uint32_t cb = ks * 32 + ((lane >> 4) << 4);
        ldm4(af[0][mt], st + 0 * GMAT + r * 80 + cb);
        ldm4(af[1][mt], st + 1 * GMAT + r * 80 + cb);
    }
    #pragma unroll
    for (int p = 0; p < 4; p++) {
        const int g = lane >> 3;
        const uint32_t nr = wc * 64 + p * 16 + (lane & 7) + ((g >> 1) << 3);
        const uint32_t cb = ks * 32 + ((g & 1) << 4);
        uint32_t t[4];
        ldm4(t, st + 2 * GMAT + nr * 80 + cb);
        bfh[2 * p][0] = t[0]; bfh[2 * p][1] = t[1];
        bfh[2 * p + 1][0] = t[2]; bfh[2 * p + 1][1] = t[3];
        ldm4(t, st + 3 * GMAT + nr * 80 + cb);
        bfl[2 * p][0] = t[0]; bfl[2 * p][1] = t[1];
        bfl[2 * p + 1][0] = t[2]; bfl[2 * p + 1][1] = t[3];
    }
}

__device__ __forceinline__ void g_do_mmas(
    float acc[2][8][4], uint32_t af[2][2][4], uint32_t bfh[8][2], uint32_t bfl[8][2])
{
    #pragma unroll
    for (int mt = 0; mt < 2; mt++)
        #pragma unroll
        for (int nt = 0; nt < 8; nt++) {
            mma16816(acc[mt][nt], af[0][mt], bfh[nt][0], bfh[nt][1]);
            mma16816(acc[mt][nt], af[0][mt], bfl[nt][0], bfl[nt][1]);
            mma16816(acc[mt][nt], af[1][mt], bfh[nt][0], bfh[nt][1]);
        }
}

__global__ __launch_bounds__(256, 2) void gemm_mma_kernel(
    const __nv_bfloat16* __restrict__ Ahi, const __nv_bfloat16* __restrict__ Alo,
    const __nv_bfloat16* __restrict__ Bhi, const __nv_bfloat16* __restrict__ Blo,
    const float* __restrict__ bias, float* __restrict__ Cf,
    __nv_bfloat16* __restrict__ Chi, __nv_bfloat16* __restrict__ Clo,
    int N, int mode)
{
    extern __shared__ __align__(128) char smem[];
    const int tid = threadIdx.x;
    const int lane = tid & 31;
    const int wid = tid >> 5;
    const int wr = wid & 3;        // m direction (4)
    const int wc = wid >> 2;       // n direction (2)
    const int row0 = blockIdx.y * 128;
    const int col0 = blockIdx.x * 128;
    const uint32_t sb = smem_u32(smem);

    g_load_stage(sb, tid, Ahi, Alo, Bhi, Blo, row0, col0, 0);
    CP_COMMIT();
    g_load_stage(sb + GSTAGE, tid, Ahi, Alo, Bhi, Blo, row0, col0, 1);
    CP_COMMIT();

    float acc[2][8][4];
    #pragma unroll
    for (int mt = 0; mt < 2; mt++)
        #pragma unroll
        for (int nt = 0; nt < 8; nt++)
            #pragma unroll
            for (int q = 0; q < 4; q++) acc[mt][nt][q] = 0.0f;

    for (int i = 0; i < GNCH; i++) {
        if (i >= GNCH - 2) CP_WAIT0(); else CP_WAIT1();
        __syncthreads();
        const uint32_t st = sb + (i & 1) * GSTAGE;

        uint32_t af[2][2][4], bfh[8][2], bfl[8][2];

        // --- first half-chunk (ks=0): load frags, MMA ---
        g_load_frags(st, 0, lane, wr, wc, af, bfh, bfl);
        g_do_mmas(acc, af, bfh, bfl);

        // --- second half-chunk (ks=1): load frags BEFORE the barrier ---
        g_load_frags(st, 1, lane, wr, wc, af, bfh, bfl);
        __syncthreads();   // all LDSM reads of this buffer done (HMMA drain not needed)

        // Prefetch chunk i+2 into this buffer; overlaps with ks=1 MMAs below.
        if (i + 2 < GNCH) {
            g_load_stage(st, tid, Ahi, Alo, Bhi, Blo, row0, col0, i + 2);
            CP_COMMIT();
        }
        g_do_mmas(acc, af, bfh, bfl);
    }

    // Epilogue
    #pragma unroll
    for (int mt = 0; mt < 2; mt++) {
        const int r = row0 + wr * 32 + mt * 16 + (lane >> 2);
        #pragma unroll
        for (int nt = 0; nt < 8; nt++) {
            const int c = col0 + wc * 64 + nt * 8 + (lane & 3) * 2;
            const float b0 = bias[c], b1 = bias[c + 1];
            const float v0 = acc[mt][nt][0] + b0, v1 = acc[mt][nt][1] + b1;
            const float v2 = acc[mt][nt][2] + b0, v3 = acc[mt][nt][3] + b1;
            if (mode == 0) {
                *(float2*)&Cf[(size_t)r * N + c]       = make_float2(v0, v1);
                *(float2*)&Cf[(size_t)(r + 8) * N + c] = make_float2(v2, v3);
            } else {
                __nv_bfloat16 h0, h1, h2, h3, l0, l1, l2, l3;
                split1(v0, h0, l0); split1(v1, h1, l1);
                split1(v2, h2, l2); split1(v3, h3, l3);
                *(uint32_t*)&Chi[(size_t)r * N + c]       = pack2(h0, h1);
                *(uint32_t*)&Clo[(size_t)r * N + c]       = pack2(l0, l1);
                *(uint32_t*)&Chi[(size_t)(r + 8) * N + c] = pack2(h2, h3);
                *(uint32_t*)&Clo[(size_t)(r + 8) * N + c] = pack2(l2, l3);
            }
        }
    }
}

// ---------------------------------------------------------------------------
// Flash attention (causal) with mma.sync split-bf16.
// 64x64 tiles, 4 warps. 3-stage K/V pipeline, ONE barrier per k-tile:
// prefetch kt+2 goes to buffer (kt+2)%3 whose readers (kt-1) are provably done.
// Q-tile order reversed so heavy causal blocks launch first.
// ---------------------------------------------------------------------------
#define FQH 0
#define FQL 8192
#define FST 16384
#define FSTAGE 32768               // Kh|Kl|Vh|Vl each 8192
#define FSMEM (FST + 3 * FSTAGE)   // 114688

__device__ __forceinline__ uint32_t fsw(int r, int j) {
    return (uint32_t)(r * 128 + ((j ^ (r & 7)) << 4));
}

__device__ __forceinline__ void f_load_kv(
    uint32_t sb, int tid,
    const __nv_bfloat16* __restrict__ qh, const __nv_bfloat16* __restrict__ ql,
    int b, int h, int k0)
{
    #pragma unroll
    for (int it = 0; it < 4; it++) {
        const int u = tid + it * 128;      // 0..511
        const int r = u >> 3;
        const int j = u & 7;
        const uint32_t off = fsw(r, j);
        const size_t gk = (size_t)(b * SEQ + k0 + r) * (3 * HID) + HID + h * DHEAD + j * 8;
        const size_t gv = gk + HID;
        cpa16(sb + 0     + off, qh + gk);
        cpa16(sb + 8192  + off, ql + gk);
        cpa16(sb + 16384 + off, qh + gv);
        cpa16(sb + 24576 + off, ql + gv);
    }
}

__global__ __launch_bounds__(128) void flash_mma_kernel(
    const __nv_bfloat16* __restrict__ qh, const __nv_bfloat16* __restrict__ ql,
    __nv_bfloat16* __restrict__ Ohi, __nv_bfloat16* __restrict__ Olo)
{
    extern __shared__ __align__(128) char smem[];
    const int tid = threadIdx.x;
    const int lane = tid & 31;
    const int wr = tid >> 5;               // warp id: 16-row band
    const int bh = blockIdx.y;
    const int b = bh >> 4;
    const int h = bh & 15;
    const int q0 = (gridDim.x - 1 - blockIdx.x) * 64;   // heavy tiles first
    const uint32_t sb = smem_u32(smem);
    const int ktiles = q0 / 64 + 1;

    // Prologue: Q + stage0 (group 0), stage1 (group 1)
    #pragma unroll
    for (int it = 0; it < 4; it++) {
        const int u = tid + it * 128;
        const int r = u >> 3;
        const int j = u & 7;
        const uint32_t off = fsw(r, j);
        const size_t gq = (size_t)(b * SEQ + q0 + r) * (3 * HID) + h * DHEAD + j * 8;
        cpa16(sb + FQH + off, qh + gq);
        cpa16(sb + FQL + off, ql + gq);
    }
    f_load_kv(sb + FST, tid, qh, ql, b, h, 0);
    CP_COMMIT();
    if (ktiles > 1) {
        f_load_kv(sb + FST + FSTAGE, tid, qh, ql, b, h, 64);
        CP_COMMIT();
    }

    uint32_t qf[2][4][4];                  // [hi/lo][kstep][4]
    float m0 = -INFINITY, m1 = -INFINITY, l0 = 0.0f, l1 = 0.0f;
    float acc[8][4];
    #pragma unroll
    for (int nt = 0; nt < 8; nt++)
        #pragma unroll
        for (int q = 0; q < 4; q++) acc[nt][q] = 0.0f;

    const int qr0 = q0 + wr * 16 + (lane >> 2);
    const int qr1 = qr0 + 8;

    int cur = 0;                           // kt % 3

    for (int kt = 0; kt < ktiles; kt++) {
        if (kt >= ktiles - 1) CP_WAIT0(); else CP_WAIT1();
        __syncthreads();                   // single barrier per iteration

        // Prefetch kt+2 into buffer (cur+2)%3 — its readers (kt-1) are done.
        if (kt + 2 < ktiles) {
            int tgt = cur + 2; if (tgt >= 3) tgt -= 3;
            f_load_kv(sb + FST + tgt * FSTAGE, tid, qh, ql, b, h, (kt + 2) * 64);
            CP_COMMIT();
        }

        const uint32_t st = sb + FST + cur * FSTAGE;
        cur = (cur == 2) ? 0 : cur + 1;

        if (kt == 0) {
            // Hoist Q fragments (loop-invariant)
            #pragma unroll
            for (int ks = 0; ks < 4; ks++) {
                const int r = wr * 16 + (lane & 15);
                const int j = ks * 2 + (lane >> 4);
                ldm4(qf[0][ks], sb + FQH + fsw(r, j));
                ldm4(qf[1][ks], sb + FQL + fsw(r, j));
            }
        }

        // ---- S = Q @ K^T (3-term split) ----
        float sf[8][4];
        #pragma unroll
        for (int nt = 0; nt < 8; nt++)
            #pragma unroll
            for (int q = 0; q < 4; q++) sf[nt][q] = 0.0f;

        #pragma unroll
        for (int ks = 0; ks < 4; ks++) {
            #pragma unroll
            for (int p = 0; p < 4; p++) {
                const int g = lane >> 3;
                const int nr = p * 16 + (lane & 7) + ((g >> 1) << 3);
                const int j = ks * 2 + (g & 1);
                uint32_t th[4], tl[4];
                ldm4(th, st + 0 + nr * 128 + (((uint32_t)(j ^ (nr & 7))) << 4));
                ldm4(tl, st + 8192 + nr * 128 + (((uint32_t)(j ^ (nr & 7))) << 4));
                mma16816(sf[2 * p],     qf[0][ks], th[0], th[1]);
                mma16816(sf[2 * p],     qf[0][ks], tl[0], tl[1]);
                mma16816(sf[2 * p],     qf[1][ks], th[0], th[1]);
                mma16816(sf[2 * p + 1], qf[0][ks], th[2], th[3]);
                mma16816(sf[2 * p + 1], qf[0][ks], tl[2], tl[3]);
                mma16816(sf[2 * p + 1], qf[1][ks], th[2], th[3]);
            }
        }

        // ---- softmax (scale, mask, online update) ----
        const int k0 = kt * 64;
        #pragma unroll
        for (int nt = 0; nt < 8; nt++)
            #pragma unroll
            for (int q = 0; q < 4; q++) sf[nt][q] *= 0.125f;

        if (kt == ktiles - 1) {  // diagonal tile
            #pragma unroll
            for (int nt = 0; nt < 8; nt++) {
                const int c = k0 + nt * 8 + (lane & 3) * 2;
                if (c > qr0)     sf[nt][0] = -INFINITY;
                if (c + 1 > qr0) sf[nt][1] = -INFINITY;
                if (c > qr1)     sf[nt][2] = -INFINITY;
                if (c + 1 > qr1) sf[nt][3] = -INFINITY;
            }
        }

        float cm0 = -INFINITY, cm1 = -INFINITY;
        #pragma unroll
        for (int nt = 0; nt < 8; nt++) {
            cm0 = fmaxf(cm0, fmaxf(sf[nt][0], sf[nt][1]));
            cm1 = fmaxf(cm1, fmaxf(sf[nt][2], sf[nt][3]));
        }
        cm0 = fmaxf(cm0, __shfl_xor_sync(0xffffffffu, cm0, 1));
        cm0 = fmaxf(cm0, __shfl_xor_sync(0xffffffffu, cm0, 2));
        cm1 = fmaxf(cm1, __shfl_xor_sync(0xffffffffu, cm1, 1));
        cm1 = fmaxf(cm1, __shfl_xor_sync(0xffffffffu, cm1, 2));

        const float mn0 = fmaxf(m0, cm0);
        const float mn1 = fmaxf(m1, cm1);
        const float al0 = __expf(m0 - mn0);
        const float al1 = __expf(m1 - mn1);
        m0 = mn0; m1 = mn1;

        float rs0 = 0.0f, rs1 = 0.0f;
        #pragma unroll
        for (int nt = 0; nt < 8; nt++) {
            sf[nt][0] = __expf(sf[nt][0] - mn0);
            sf[nt][1] = __expf(sf[nt][1] - mn0);
            sf[nt][2] = __expf(sf[nt][2] - mn1);
            sf[nt][3] = __expf(sf[nt][3] - mn1);
            rs0 += sf[nt][0] + sf[nt][1];
            rs1 += sf[nt][2] + sf[nt][3];
        }
        rs0 += __shfl_xor_sync(0xffffffffu, rs0, 1);
        rs0 += __shfl_xor_sync(0xffffffffu, rs0, 2);
        rs1 += __shfl_xor_sync(0xffffffffu, rs1, 1);
        rs1 += __shfl_xor_sync(0xffffffffu, rs1, 2);
        l0 = l0 * al0 + rs0;
        l1 = l1 * al1 + rs1;

        #pragma unroll
        for (int nt = 0; nt < 8; nt++) {
            acc[nt][0] *= al0; acc[nt][1] *= al0;
            acc[nt][2] *= al1; acc[nt][3] *= al1;
        }

        // ---- pack P into A fragments (hi/lo) ----
        uint32_t ph[4][4], pl[4][4];
        #pragma unroll
        for (int ks = 0; ks < 4; ks++) {
            __nv_bfloat16 h00, h01, h10, h11, h20, h21, h30, h31;
            __nv_bfloat16 e00, e01, e10, e11, e20, e21, e30, e31;
            split1(sf[2 * ks][0], h00, e00); split1(sf[2 * ks][1], h01, e01);
            split1(sf[2 * ks][2], h10, e10); split1(sf[2 * ks][3], h11, e11);
            split1(sf[2 * ks + 1][0], h20, e20); split1(sf[2 * ks + 1][1], h21, e21);
            split1(sf[2 * ks + 1][2], h30, e30); split1(sf[2 * ks + 1][3], h31, e31);
            ph[ks][0] = pack2(h00, h01); ph[ks][1] = pack2(h10, h11);
            ph[ks][2] = pack2(h20, h21); ph[ks][3] = pack2(h30, h31);
            pl[ks][0] = pack2(e00, e01); pl[ks][1] = pack2(e10, e11);
            pl[ks][2] = pack2(e20, e21); pl[ks][3] = pack2(e30, e31);
        }

        // ---- O += P @ V (3-term split) ----
        #pragma unroll
        for (int ks = 0; ks < 4; ks++) {
            #pragma unroll
            for (int dp = 0; dp < 4; dp++) {
                const int g = lane >> 3;
                const int krow = ks * 16 + (lane & 7) + ((g & 1) << 3);
                const int j = dp * 2 + (g >> 1);
                uint32_t th[4], tl[4];
                ldm4t(th, st + 16384 + krow * 128 + (((uint32_t)(j ^ (krow & 7))) << 4));
                ldm4t(tl, st + 24576 + krow * 128 + (((uint32_t)(j ^ (krow & 7))) << 4));
                mma16816(acc[2 * dp],     ph[ks], th[0], th[1]);
                mma16816(acc[2 * dp],     ph[ks], tl[0], tl[1]);
                mma16816(acc[2 * dp],     pl[ks], th[0], th[1]);
                mma16816(acc[2 * dp + 1], ph[ks], th[2], th[3]);
                mma16816(acc[2 * dp + 1], ph[ks], tl[2], tl[3]);
                mma16816(acc[2 * dp + 1], pl[ks], th[2], th[3]);
            }
        }
        // no end-of-iteration barrier: 3-stage ring guarantees buffer safety
    }

    // Epilogue: normalize, split to bf16 hi/lo
    const float i0 = 1.0f / l0;
    const float i1 = 1.0f / l1;
    #pragma unroll
    for (int nt = 0; nt < 8; nt++) {
        const int c = h * DHEAD + nt * 8 + (lane & 3) * 2;
        const size_t o0 = (size_t)(b * SEQ + qr0) * HID + c;
        const size_t o1 = (size_t)(b * SEQ + qr1) * HID + c;
        __nv_bfloat16 h0, h1, h2, h3, e0, e1, e2, e3;
        split1(acc[nt][0] * i0, h0, e0);
        split1(acc[nt][1] * i0, h1, e1);
        split1(acc[nt][2] * i1, h2, e2);
        split1(acc[nt][3] * i1, h3, e3);
        *(uint32_t*)&Ohi[o0] = pack2(h0, h1);
        *(uint32_t*)&Olo[o0] = pack2(e0, e1);
        *(uint32_t*)&Ohi[o1] = pack2(h2, h3);
        *(uint32_t*)&Olo[o1] = pack2(e2, e3);
    }
}

// ---------------------------------------------------------------------------
// Launch
// ---------------------------------------------------------------------------
extern "C" void kernel_launch(void* const* d_in, const int* in_sizes, int n_in,
                              void* d_out, int out_size)
{
    const float* x      = (const float*)d_in[0];   // [B,S,H]
    const float* w_attn = (const float*)d_in[1];   // [H, 3H]
    const float* b_attn = (const float*)d_in[2];   // [3H]
    const float* w_proj = (const float*)d_in[3];   // [H, H]
    const float* b_proj = (const float*)d_in[4];   // [H]
    float* out = (float*)d_out;                    // [B,S,H]

    __nv_bfloat16 *xhi, *xlo, *qkvh, *qkvl, *ahi, *alo, *wahi, *walo, *wphi, *wplo;
    cudaGetSymbolAddress((void**)&xhi,  g_xhi);
    cudaGetSymbolAddress((void**)&xlo,  g_xlo);
    cudaGetSymbolAddress((void**)&qkvh, g_qkvh);
    cudaGetSymbolAddress((void**)&qkvl, g_qkvl);
    cudaGetSymbolAddress((void**)&ahi,  g_ahi);
    cudaGetSymbolAddress((void**)&alo,  g_alo);
    cudaGetSymbolAddress((void**)&wahi, g_wahi);
    cudaGetSymbolAddress((void**)&walo, g_walo);
    cudaGetSymbolAddress((void**)&wphi, g_wphi);
    cudaGetSymbolAddress((void**)&wplo, g_wplo);

    cudaFuncSetAttribute(gemm_mma_kernel,
                         cudaFuncAttributeMaxDynamicSharedMemorySize, GSMEM);
    cudaFuncSetAttribute(flash_mma_kernel,
                         cudaFuncAttributeMaxDynamicSharedMemorySize, FSMEM);

    // 0) Conversions
    {
        const int n4 = MTOT * HID / 4;
        split_kernel<<<n4 / 256, 256>>>(x, xhi, xlo, n4);
        tsplit_kernel<<<dim3(3 * HID / 32, HID / 32), 256>>>(w_attn, wahi, walo, HID, 3 * HID);
        tsplit_kernel<<<dim3(HID / 32, HID / 32), 256>>>(w_proj, wphi, wplo, HID, HID);
    }

    // 1) QKV projection -> split bf16 output
    gemm_mma_kernel<<<dim3(3 * HID / 128, MTOT / 128), 256, GSMEM>>>(
        xhi, xlo, wahi, walo, b_attn, nullptr, qkvh, qkvl, 3 * HID, 1);

    // 2) Flash attention -> split bf16 output
    flash_mma_kernel<<<dim3(SEQ / 64, BATCH * NHEAD), 128, FSMEM>>>(
        qkvh, qkvl, ahi, alo);

    // 3) Output projection -> fp32
    gemm_mma_kernel<<<dim3(HID / 128, MTOT / 128), 256, GSMEM>>>(
        ahi, alo, wphi, wplo, b_proj, out, nullptr, nullptr, HID, 0);
}